// round 2
// baseline (speedup 1.0000x reference)
#include <cuda_runtime.h>

// CostVolume1D: out[n,d,h,w] = (1/C) * sum_c f1[n,c,h,w] * f2pad[n,c,h,w+d],  d in [0,9)
// f1,f2: [N=4, C=128, H=192, W=640] fp32.  f2 zero-padded by D=4 on each side of W.

#define Nn   4
#define Cc   128
#define Hh   192
#define Ww   640
#define Dd   4
#define NS   (2*Dd + 1)      // 9
#define TPB  128
#define OPT  5               // outputs per thread: 128*5 = 640 = W
#define CCH  8               // channels per smem chunk
#define W2   (Ww + 2*Dd)     // 648 (x4B = 2592B, multiple of 16 -> float4-aligned rows)

__global__ __launch_bounds__(TPB)
void costvol1d_kernel(const float* __restrict__ f1,
                      const float* __restrict__ f2,
                      float* __restrict__ out)
{
    __shared__ __align__(16) float s1[CCH][Ww];
    __shared__ __align__(16) float s2[CCH][W2];

    const int bx  = blockIdx.x;          // 0 .. N*H-1
    const int n   = bx / Hh;
    const int h   = bx - n * Hh;
    const int tid = threadIdx.x;
    const int w0  = tid * OPT;           // first owned output column

    // Zero the 8 halo floats of every s2 row ONCE (they are never overwritten:
    // fills only write [Dd, Dd+Ww)). Ordered before first read by the
    // __syncthreads() at the top of the first chunk iteration.
    if (tid < CCH * 2 * Dd) {
        const int cc = tid / (2 * Dd);
        const int k  = tid % (2 * Dd);
        const int pos = (k < Dd) ? k : (Ww + k);   // 0..3 and 644..647
        s2[cc][pos] = 0.0f;
    }

    float acc[OPT * NS];
    #pragma unroll
    for (int i = 0; i < OPT * NS; i++) acc[i] = 0.0f;

    // element (n,c,h,w) at ((n*C + c)*H + h)*W + w
    const size_t rowbase = (size_t)n * Cc * Hh * Ww + (size_t)h * Ww;

    for (int c0 = 0; c0 < Cc; c0 += CCH) {
        __syncthreads();   // previous chunk's compute done before refill

        // Coalesced float4 fills of both rows for CCH channels.
        #pragma unroll
        for (int cc = 0; cc < CCH; cc++) {
            const int c = c0 + cc;
            const float4* src1 = (const float4*)(f1 + rowbase + (size_t)c * Hh * Ww);
            const float4* src2 = (const float4*)(f2 + rowbase + (size_t)c * Hh * Ww);
            float4* dst1 = (float4*)(&s1[cc][0]);
            float4* dst2 = (float4*)(&s2[cc][Dd]);   // base+16B, rows 16B-aligned
            for (int i = tid; i < Ww / 4; i += TPB) {   // 160 float4 / row
                dst1[i] = src1[i];
                dst2[i] = src2[i];
            }
        }
        __syncthreads();

        // Compute: per channel, 5 f1 reads + 13-wide sliding f2 window -> 45 FMA.
        // LDS addresses step 5 floats/lane; gcd(5,32)=1 -> conflict-free.
        #pragma unroll
        for (int cc = 0; cc < CCH; cc++) {
            float f1v[OPT];
            float f2v[OPT + 2 * Dd];
            #pragma unroll
            for (int j = 0; j < OPT; j++)          f1v[j] = s1[cc][w0 + j];
            #pragma unroll
            for (int k = 0; k < OPT + 2 * Dd; k++) f2v[k] = s2[cc][w0 + k];

            #pragma unroll
            for (int j = 0; j < OPT; j++) {
                #pragma unroll
                for (int d = 0; d < NS; d++) {
                    acc[j * NS + d] = fmaf(f1v[j], f2v[j + d], acc[j * NS + d]);
                }
            }
        }
    }

    // Epilogue: mean over channels, write out[n,d,h,w].
    const float inv = 1.0f / (float)Cc;
    #pragma unroll
    for (int d = 0; d < NS; d++) {
        float* orow = out + ((size_t)(n * NS + d) * Hh + h) * Ww;
        #pragma unroll
        for (int j = 0; j < OPT; j++) {
            orow[w0 + j] = acc[j * NS + d] * inv;
        }
    }
}

extern "C" void kernel_launch(void* const* d_in, const int* in_sizes, int n_in,
                              void* d_out, int out_size)
{
    const float* f1 = (const float*)d_in[0];
    const float* f2 = (const float*)d_in[1];
    float* out = (float*)d_out;
    (void)in_sizes; (void)n_in; (void)out_size;

    dim3 grid(Nn * Hh);   // 768 blocks, one per (n,h) row
    dim3 block(TPB);
    costvol1d_kernel<<<grid, block>>>(f1, f2, out);
}

// round 3
// speedup vs baseline: 3.0236x; 3.0236x over previous
#include <cuda_runtime.h>

// CostVolume1D: out[n,d,h,w] = (1/C) * sum_c f1[n,c,h,w] * f2pad[n,c,h,w+d-4]
// f1,f2: [4,128,192,640] fp32. Barrier-free, smem-free streaming kernel:
// each thread owns one float4 of w, accumulates all 9 shifts in registers.

#define Nn   4
#define Cc   128
#define Hh   192
#define Ww   640
#define Dd   4
#define NS   (2*Dd + 1)       // 9
#define TPB  128
#define VW   (Ww / 4)         // 160 float4 per row
#define CH4  ((size_t)Hh * VW) // channel stride in float4 units (30720)

__global__ __launch_bounds__(TPB)
void costvol1d_kernel(const float4* __restrict__ f1,
                      const float4* __restrict__ f2,
                      float* __restrict__ out)
{
    const int gid = blockIdx.x * TPB + threadIdx.x;   // 0 .. N*H*VW-1 = 122879
    const int v   = gid % VW;          // float4 index within row
    const int row = gid / VW;          // n*Hh + h
    const int n   = row / Hh;
    const int h   = row % Hh;

    const bool pm = (v > 0);           // left-edge window valid?
    const bool pp = (v < VW - 1);      // right-edge window valid?

    // base offsets in float4 units for channel 0
    const size_t b1 = ((size_t)n * Cc * Hh + h) * VW + v;
    const size_t b2 = b1;              // same layout for f2

    float acc[NS * 4];
    #pragma unroll
    for (int i = 0; i < NS * 4; i++) acc[i] = 0.0f;

    const float4 z4 = make_float4(0.f, 0.f, 0.f, 0.f);

    #pragma unroll 4
    for (int c = 0; c < Cc; c++) {
        const size_t o1 = b1 + (size_t)c * CH4;
        const size_t o2 = b2 + (size_t)c * CH4;

        const float4 a  = f1[o1];
        const float4 c0 = f2[o2];
        const float4 cm = pm ? f2[o2 - 1] : z4;   // f2[w-4..w-1] (zero pad at w=0)
        const float4 cp = pp ? f2[o2 + 1] : z4;   // f2[w+4..w+7] (zero pad at w=636)

        // window win[k] = f2pad[w-4+k], k=0..11
        float win[12];
        win[0] = cm.x; win[1] = cm.y; win[2]  = cm.z; win[3]  = cm.w;
        win[4] = c0.x; win[5] = c0.y; win[6]  = c0.z; win[7]  = c0.w;
        win[8] = cp.x; win[9] = cp.y; win[10] = cp.z; win[11] = cp.w;

        float av[4];
        av[0] = a.x; av[1] = a.y; av[2] = a.z; av[3] = a.w;

        // out(w+j, shift d) uses f2pad[w+j+d-4] = win[j+d]
        #pragma unroll
        for (int d = 0; d < NS; d++) {
            #pragma unroll
            for (int j = 0; j < 4; j++) {
                acc[d * 4 + j] = fmaf(av[j], win[j + d], acc[d * 4 + j]);
            }
        }
    }

    // Epilogue: channel mean, vectorized stores. out[n][d][h][w..w+3]
    const float inv = 1.0f / (float)Cc;
    float4* o4 = (float4*)out;
    #pragma unroll
    for (int d = 0; d < NS; d++) {
        float4 o;
        o.x = acc[d * 4 + 0] * inv;
        o.y = acc[d * 4 + 1] * inv;
        o.z = acc[d * 4 + 2] * inv;
        o.w = acc[d * 4 + 3] * inv;
        o4[((size_t)(n * NS + d) * Hh + h) * VW + v] = o;
    }
}

extern "C" void kernel_launch(void* const* d_in, const int* in_sizes, int n_in,
                              void* d_out, int out_size)
{
    const float4* f1 = (const float4*)d_in[0];
    const float4* f2 = (const float4*)d_in[1];
    float* out = (float*)d_out;
    (void)in_sizes; (void)n_in; (void)out_size;

    const int total = Nn * Hh * VW;          // 122880 threads, 1 float4 each
    dim3 grid(total / TPB);                  // 960 blocks
    dim3 block(TPB);
    costvol1d_kernel<<<grid, block>>>(f1, f2, out);
}